// round 6
// baseline (speedup 1.0000x reference)
#include <cuda_runtime.h>
#include <cuda_fp16.h>
#include <math.h>

#define N_NODES 50000
#define N_EDGES 1600000
#define BATCH   2
#define C       64
#define NBLK    ((N_NODES + 255) / 256)

// ---- scratch ----
__device__ int    g_cnt[N_NODES];
__device__ int    g_off[N_NODES + 1];
__device__ int    g_cursor[N_NODES];
__device__ int    g_bsum[NBLK];
__device__ float  g_dis[N_NODES];
// interleaved per (batch,node) row: [xc: 64 halfs][xd: 64 halfs] = 256 B
__device__ __align__(16) __half g_xi[(size_t)BATCH * N_NODES * 2 * C];
__device__ float2 g_ep0[N_EDGES];
__device__ float2 g_ep1[N_EDGES];
__device__ int    g_esrc[N_EDGES];
__device__ int    g_is64;

// ---- packed f32x2 helpers ----
__device__ __forceinline__ unsigned long long pk2(float x, float y) {
    unsigned long long r;
    asm("mov.b64 %0, {%1,%2};" : "=l"(r) : "f"(x), "f"(y));
    return r;
}
__device__ __forceinline__ void upk2(unsigned long long v, float& x, float& y) {
    asm("mov.b64 {%0,%1}, %2;" : "=f"(x), "=f"(y) : "l"(v));
}
__device__ __forceinline__ void fma2(unsigned long long& c,
                                     unsigned long long a,
                                     unsigned long long b) {
    asm("fma.rn.f32x2 %0, %1, %2, %0;" : "+l"(c) : "l"(a), "l"(b));
}
__device__ __forceinline__ float tanh_fast(float x) {
    asm("tanh.approx.f32 %0, %0;" : "+f"(x));
    return x;
}

// ---------------------------------------------------------------------------
__global__ void detect_zero_kernel(const unsigned int* __restrict__ w) {
    int i = blockIdx.x * blockDim.x + threadIdx.x;
    if (i < N_NODES) g_cnt[i] = 0;
    if (blockIdx.x == 0) {
        __shared__ unsigned int acc;
        if (threadIdx.x == 0) acc = 0u;
        __syncthreads();
        unsigned int v = 0u;
        for (int j = threadIdx.x; j < 4096; j += blockDim.x)
            v |= w[(size_t)2 * j * 97 + 1];
        atomicOr(&acc, v);
        __syncthreads();
        if (threadIdx.x == 0) g_is64 = (acc == 0u) ? 1 : 0;
    }
}

__device__ __forceinline__ int load_idx(const int* __restrict__ ei, size_t e) {
    return g_is64 ? ei[2 * e] : ei[e];
}

// 2 edges per thread, one vector load of targets
__global__ void hist_kernel(const int* __restrict__ ei) {
    int e2 = (blockIdx.x * blockDim.x + threadIdx.x) * 2;
    if (e2 >= N_EDGES) return;
    int t0, t1;
    if (g_is64) {
        const int4 v = *(const int4*)(ei + 2 * ((size_t)N_EDGES + e2));
        t0 = v.x; t1 = v.z;
    } else {
        const int2 v = *(const int2*)(ei + (size_t)N_EDGES + e2);
        t0 = v.x; t1 = v.y;
    }
    atomicAdd(&g_cnt[t0], 1);
    atomicAdd(&g_cnt[t1], 1);
}

// ---------------------------------------------------------------------------
__device__ __forceinline__ int warp_incl_scan(int x) {
#pragma unroll
    for (int d = 1; d < 32; d <<= 1) {
        int y = __shfl_up_sync(0xffffffffu, x, d);
        if ((threadIdx.x & 31) >= d) x += y;
    }
    return x;
}

__global__ void __launch_bounds__(256) scan_local_kernel() {
    int i = blockIdx.x * 256 + threadIdx.x;
    int v = (i < N_NODES) ? g_cnt[i] : 0;
    int lane = threadIdx.x & 31, wid = threadIdx.x >> 5;
    int x = warp_incl_scan(v);
    __shared__ int wsum[8];
    if (lane == 31) wsum[wid] = x;
    __syncthreads();
    if (wid == 0) {
        int s = (lane < 8) ? wsum[lane] : 0;
#pragma unroll
        for (int d = 1; d < 8; d <<= 1) {
            int y = __shfl_up_sync(0xffffffffu, s, d);
            if (lane >= d) s += y;
        }
        if (lane < 8) wsum[lane] = s;
    }
    __syncthreads();
    int incl = x + (wid > 0 ? wsum[wid - 1] : 0);
    if (i < N_NODES) g_off[i] = incl - v;
    if (threadIdx.x == 255) g_bsum[blockIdx.x] = incl;
}

// single block: scan block sums, then finalize all nodes (fused)
__global__ void __launch_bounds__(256) scan_block_fin_kernel() {
    __shared__ int bpre[NBLK];
    int t = threadIdx.x;
    {
        int v = (t < NBLK) ? g_bsum[t] : 0;
        int lane = t & 31, wid = t >> 5;
        int x = warp_incl_scan(v);
        __shared__ int wsum[8];
        if (lane == 31) wsum[wid] = x;
        __syncthreads();
        if (wid == 0) {
            int s = (lane < 8) ? wsum[lane] : 0;
#pragma unroll
            for (int d = 1; d < 8; d <<= 1) {
                int y = __shfl_up_sync(0xffffffffu, s, d);
                if (lane >= d) s += y;
            }
            if (lane < 8) wsum[lane] = s;
        }
        __syncthreads();
        int incl = x + (wid > 0 ? wsum[wid - 1] : 0);
        if (t < NBLK) bpre[t] = incl - v;
    }
    __syncthreads();
#pragma unroll 4
    for (int i = t; i < N_NODES; i += 256) {
        int off = g_off[i] + bpre[i >> 8];
        g_off[i] = off;
        g_cursor[i] = off;
        g_dis[i] = rsqrtf((float)(g_cnt[i] + 1));
    }
    if (t == 0) g_off[N_NODES] = N_EDGES;
}

// ---------------------------------------------------------------------------
__global__ void __launch_bounds__(256)
fill_kernel(const int* __restrict__ ei,
            const float* __restrict__ fdo,
            const float* __restrict__ fluxes) {
    int e = blockIdx.x * blockDim.x + threadIdx.x;
    if (e >= N_EDGES) return;
    int s = load_idx(ei, e);
    int t = load_idx(ei, (size_t)N_EDGES + e);

    int pos = atomicAdd(&g_cursor[t], 1);

    const float f0   = fdo[e];
    const float norm = g_dis[s] * g_dis[t];

    const float k0 = 0.5f * (1.0f + tanh_fast(fluxes[s] * fluxes[t]));
    const float k1 = 0.5f * (1.0f + tanh_fast(fluxes[N_NODES + s] * fluxes[N_NODES + t]));
    const float fb0 = k0 * f0 + (1.0f - k0) * (1.0f - f0);
    const float fb1 = k1 * f0 + (1.0f - k1) * (1.0f - f0);

    g_ep0[pos] = make_float2(norm * (1.0f - fb0), norm * fb0);
    g_ep1[pos] = make_float2(norm * (1.0f - fb1), norm * fb1);
    g_esrc[pos] = s;
}

// ---------------------------------------------------------------------------
// Dual GEMM -> interleaved fp16 rows [xc(64)|xd(64)]. FFMA2-packed.
// ---------------------------------------------------------------------------
__global__ void __launch_bounds__(256)
gemm_kernel(const float* __restrict__ x,
            const float* __restrict__ Wc,
            const float* __restrict__ Wd) {
    const int o  = threadIdx.x >> 2;
    const int kg = threadIdx.x & 3;

    unsigned long long wp[16];
#pragma unroll
    for (int i = 0; i < 16; i++)
        wp[i] = pk2(Wc[o * C + kg * 16 + i], Wd[o * C + kg * 16 + i]);

    __shared__ __align__(16) float xs[4][C];
    const int M = BATCH * N_NODES;
    const int lr = threadIdx.x >> 6;
    const int lc = threadIdx.x & 63;

    for (int m0 = blockIdx.x * 4; m0 < M; m0 += gridDim.x * 4) {
        __syncthreads();
        xs[lr][lc] = x[(size_t)(m0 + lr) * C + lc];
        __syncthreads();

#pragma unroll
        for (int r2 = 0; r2 < 4; r2++) {
            const float4* xp = (const float4*)&xs[r2][kg * 16];
            unsigned long long acc = 0ull;
#pragma unroll
            for (int j = 0; j < 4; j++) {
                float4 xv = xp[j];
                fma2(acc, pk2(xv.x, xv.x), wp[4 * j + 0]);
                fma2(acc, pk2(xv.y, xv.y), wp[4 * j + 1]);
                fma2(acc, pk2(xv.z, xv.z), wp[4 * j + 2]);
                fma2(acc, pk2(xv.w, xv.w), wp[4 * j + 3]);
            }
            float sc, sd;
            upk2(acc, sc, sd);
            sc += __shfl_xor_sync(0xffffffffu, sc, 1);
            sc += __shfl_xor_sync(0xffffffffu, sc, 2);
            sd += __shfl_xor_sync(0xffffffffu, sd, 1);
            sd += __shfl_xor_sync(0xffffffffu, sd, 2);
            float sc2 = __shfl_xor_sync(0xffffffffu, sc, 4);
            float sd2 = __shfl_xor_sync(0xffffffffu, sd, 4);

            if (kg == 0 && (o & 1) == 0) {
                __half* row = g_xi + (size_t)(m0 + r2) * (2 * C);
                *(__half2*)(row + o)     = __floats2half2_rn(sc, sc2);
                *(__half2*)(row + C + o) = __floats2half2_rn(sd, sd2);
            }
        }
    }
}

// ---------------------------------------------------------------------------
// Gather: one warp per (node,batch), batch-major. Four 8-lane groups each
// process TWO edges per iteration (8 edges/warp/iter); lane covers 8 channels.
// Metadata software-pipelined one iteration ahead.
// ---------------------------------------------------------------------------
__device__ __forceinline__ void edge_fma(unsigned long long& a0, unsigned long long& a1,
                                         unsigned long long& a2, unsigned long long& a3,
                                         uint4 A, uint4 D, float2 cf) {
    const unsigned long long cc = pk2(cf.x, cf.x);
    const unsigned long long cd = pk2(cf.y, cf.y);
    float2 t;
    t = __half22float2(*(const __half2*)&A.x); fma2(a0, pk2(t.x, t.y), cc);
    t = __half22float2(*(const __half2*)&A.y); fma2(a1, pk2(t.x, t.y), cc);
    t = __half22float2(*(const __half2*)&A.z); fma2(a2, pk2(t.x, t.y), cc);
    t = __half22float2(*(const __half2*)&A.w); fma2(a3, pk2(t.x, t.y), cc);
    t = __half22float2(*(const __half2*)&D.x); fma2(a0, pk2(t.x, t.y), cd);
    t = __half22float2(*(const __half2*)&D.y); fma2(a1, pk2(t.x, t.y), cd);
    t = __half22float2(*(const __half2*)&D.z); fma2(a2, pk2(t.x, t.y), cd);
    t = __half22float2(*(const __half2*)&D.w); fma2(a3, pk2(t.x, t.y), cd);
}

__global__ void __launch_bounds__(256)
gather_kernel(const float* __restrict__ bias, float* __restrict__ out) {
    const int w = (int)((blockIdx.x * blockDim.x + threadIdx.x) >> 5);
    if (w >= BATCH * N_NODES) return;
    const int b    = (w < N_NODES) ? 0 : 1;
    const int n    = (w < N_NODES) ? w : (w - N_NODES);
    const int lane = threadIdx.x & 31;
    const int g    = lane >> 3;        // edge group 0..3
    const int l8   = lane & 7;         // 8 channels: l8*8 .. +8

    const int beg = g_off[n];
    const int end = g_off[n + 1];

    const __half*  __restrict__ xib = g_xi + (size_t)b * N_NODES * (2 * C);
    const float2*  __restrict__ ep  = b ? g_ep1 : g_ep0;

    unsigned long long a0 = 0ull, a1 = 0ull, a2 = 0ull, a3 = 0ull;

    if (g == 0) {   // self-loop + bias init
        const float dv  = g_dis[n];
        const float nrm = dv * dv;
        const float4 b0 = *(const float4*)(bias + l8 * 8);
        const float4 b1 = *(const float4*)(bias + l8 * 8 + 4);
        const uint4  xh = *(const uint4*)(xib + (size_t)n * (2 * C) + l8 * 8);
        const float2 x0 = __half22float2(*(const __half2*)&xh.x);
        const float2 x1 = __half22float2(*(const __half2*)&xh.y);
        const float2 x2 = __half22float2(*(const __half2*)&xh.z);
        const float2 x3 = __half22float2(*(const __half2*)&xh.w);
        a0 = pk2(fmaf(nrm, x0.x, b0.x), fmaf(nrm, x0.y, b0.y));
        a1 = pk2(fmaf(nrm, x1.x, b0.z), fmaf(nrm, x1.y, b0.w));
        a2 = pk2(fmaf(nrm, x2.x, b1.x), fmaf(nrm, x2.y, b1.y));
        a3 = pk2(fmaf(nrm, x3.x, b1.z), fmaf(nrm, x3.y, b1.w));
    }

    int i = beg + g;                   // group-strided; pairs (i, i+4), stride 8
    if (i < end) {
        int    s0 = g_esrc[i];
        float2 c0 = ep[i];
        int    s1 = 0;  float2 c1 = make_float2(0.f, 0.f);
        const bool has1_init = (i + 4 < end);
        if (has1_init) { s1 = g_esrc[i + 4]; c1 = ep[i + 4]; }

        while (i < end) {
            const int inext = i + 8;
            int    ns0 = 0, ns1 = 0;
            float2 nc0 = make_float2(0.f, 0.f), nc1 = make_float2(0.f, 0.f);
            if (inext < end)     { ns0 = g_esrc[inext];     nc0 = ep[inext]; }
            if (inext + 4 < end) { ns1 = g_esrc[inext + 4]; nc1 = ep[inext + 4]; }

            // issue all row loads first (max loads in flight)
            const __half* r0 = xib + (size_t)s0 * (2 * C) + l8 * 8;
            const uint4 A0 = *(const uint4*)(r0);
            const uint4 D0 = *(const uint4*)(r0 + C);
            const bool has1 = (i + 4 < end);
            uint4 A1, D1;
            if (has1) {
                const __half* r1 = xib + (size_t)s1 * (2 * C) + l8 * 8;
                A1 = *(const uint4*)(r1);
                D1 = *(const uint4*)(r1 + C);
            }

            edge_fma(a0, a1, a2, a3, A0, D0, c0);
            if (has1) edge_fma(a0, a1, a2, a3, A1, D1, c1);

            i = inext; s0 = ns0; c0 = nc0; s1 = ns1; c1 = nc1;
        }
    }

    // reduce the 4 groups
    float f0, f1, f2, f3, f4, f5, f6, f7;
    upk2(a0, f0, f1); upk2(a1, f2, f3); upk2(a2, f4, f5); upk2(a3, f6, f7);
#pragma unroll
    for (int d = 8; d <= 16; d <<= 1) {
        f0 += __shfl_xor_sync(0xffffffffu, f0, d);
        f1 += __shfl_xor_sync(0xffffffffu, f1, d);
        f2 += __shfl_xor_sync(0xffffffffu, f2, d);
        f3 += __shfl_xor_sync(0xffffffffu, f3, d);
        f4 += __shfl_xor_sync(0xffffffffu, f4, d);
        f5 += __shfl_xor_sync(0xffffffffu, f5, d);
        f6 += __shfl_xor_sync(0xffffffffu, f6, d);
        f7 += __shfl_xor_sync(0xffffffffu, f7, d);
    }

    if (g == 0) {
        float* orow = out + ((size_t)b * N_NODES + n) * C + l8 * 8;
        *(float4*)(orow)     = make_float4(f0, f1, f2, f3);
        *(float4*)(orow + 4) = make_float4(f4, f5, f6, f7);
    }
}

// ---------------------------------------------------------------------------
extern "C" void kernel_launch(void* const* d_in, const int* in_sizes, int n_in,
                              void* d_out, int out_size) {
    const float* x    = (const float*)d_in[0];
    const int*   ei   = (const int*)d_in[1];
    const float* fdo  = (const float*)d_in[2];
    const float* flux = (const float*)d_in[3];
    const float* Wc   = (const float*)d_in[4];
    const float* Wd   = (const float*)d_in[5];
    const float* bias = (const float*)d_in[6];
    float* out = (float*)d_out;

    static cudaStream_t s2 = nullptr;
    static cudaEvent_t evFork = nullptr, evJoin = nullptr;
    if (!s2) {
        cudaStreamCreateWithFlags(&s2, cudaStreamNonBlocking);
        cudaEventCreateWithFlags(&evFork, cudaEventDisableTiming);
        cudaEventCreateWithFlags(&evJoin, cudaEventDisableTiming);
    }

    cudaEventRecord(evFork, 0);
    cudaStreamWaitEvent(s2, evFork, 0);
    gemm_kernel<<<2960, 256, 0, s2>>>(x, Wc, Wd);
    cudaEventRecord(evJoin, s2);

    detect_zero_kernel<<<NBLK, 256>>>((const unsigned int*)ei);
    hist_kernel<<<(N_EDGES / 2 + 255) / 256, 256>>>(ei);
    scan_local_kernel<<<NBLK, 256>>>();
    scan_block_fin_kernel<<<1, 256>>>();
    fill_kernel<<<(N_EDGES + 255) / 256, 256>>>(ei, fdo, flux);

    cudaStreamWaitEvent(0, evJoin, 0);
    gather_kernel<<<(BATCH * N_NODES * 32 + 255) / 256, 256>>>(bias, out);
}

// round 7
// speedup vs baseline: 1.2131x; 1.2131x over previous
#include <cuda_runtime.h>
#include <cuda_fp16.h>
#include <math.h>

#define N_NODES 50000
#define N_EDGES 1600000
#define BATCH   2
#define C       64
#define NBLK    ((N_NODES + 255) / 256)

// ---- scratch ----
__device__ int    g_cnt[N_NODES];
__device__ int    g_off[N_NODES + 1];
__device__ int    g_cursor[N_NODES];
__device__ int    g_bsum[NBLK];
__device__ int    g_bpre[NBLK];
__device__ float  g_dis[N_NODES];
// interleaved per (batch,node) row: [xc: 64 halfs][xd: 64 halfs] = 256 B
__device__ __align__(16) __half g_xi[(size_t)BATCH * N_NODES * 2 * C];
// packed edge metadata per batch: {src(int bits), cC, cD, unused}
__device__ float4 g_em0[N_EDGES];
__device__ float4 g_em1[N_EDGES];
__device__ int    g_is64;

// ---- packed f32x2 helpers ----
__device__ __forceinline__ unsigned long long pk2(float x, float y) {
    unsigned long long r;
    asm("mov.b64 %0, {%1,%2};" : "=l"(r) : "f"(x), "f"(y));
    return r;
}
__device__ __forceinline__ void upk2(unsigned long long v, float& x, float& y) {
    asm("mov.b64 {%0,%1}, %2;" : "=f"(x), "=f"(y) : "l"(v));
}
__device__ __forceinline__ void fma2(unsigned long long& c,
                                     unsigned long long a,
                                     unsigned long long b) {
    asm("fma.rn.f32x2 %0, %1, %2, %0;" : "+l"(c) : "l"(a), "l"(b));
}
__device__ __forceinline__ float tanh_fast(float x) {
    asm("tanh.approx.f32 %0, %0;" : "+f"(x));
    return x;
}

// ---------------------------------------------------------------------------
__global__ void detect_zero_kernel(const unsigned int* __restrict__ w) {
    int i = blockIdx.x * blockDim.x + threadIdx.x;
    if (i < N_NODES) g_cnt[i] = 0;
    if (blockIdx.x == 0) {
        __shared__ unsigned int acc;
        if (threadIdx.x == 0) acc = 0u;
        __syncthreads();
        unsigned int v = 0u;
        for (int j = threadIdx.x; j < 4096; j += blockDim.x)
            v |= w[(size_t)2 * j * 97 + 1];
        atomicOr(&acc, v);
        __syncthreads();
        if (threadIdx.x == 0) g_is64 = (acc == 0u) ? 1 : 0;
    }
}

__device__ __forceinline__ int load_idx(const int* __restrict__ ei, size_t e) {
    return g_is64 ? ei[2 * e] : ei[e];
}

// 2 edges per thread, one vector load of targets
__global__ void hist_kernel(const int* __restrict__ ei) {
    int e2 = (blockIdx.x * blockDim.x + threadIdx.x) * 2;
    if (e2 >= N_EDGES) return;
    int t0, t1;
    if (g_is64) {
        const int4 v = *(const int4*)(ei + 2 * ((size_t)N_EDGES + e2));
        t0 = v.x; t1 = v.z;
    } else {
        const int2 v = *(const int2*)(ei + (size_t)N_EDGES + e2);
        t0 = v.x; t1 = v.y;
    }
    atomicAdd(&g_cnt[t0], 1);
    atomicAdd(&g_cnt[t1], 1);
}

// ---------------------------------------------------------------------------
__device__ __forceinline__ int warp_incl_scan(int x) {
#pragma unroll
    for (int d = 1; d < 32; d <<= 1) {
        int y = __shfl_up_sync(0xffffffffu, x, d);
        if ((threadIdx.x & 31) >= d) x += y;
    }
    return x;
}

__global__ void __launch_bounds__(256) scan_local_kernel() {
    int i = blockIdx.x * 256 + threadIdx.x;
    int v = (i < N_NODES) ? g_cnt[i] : 0;
    int lane = threadIdx.x & 31, wid = threadIdx.x >> 5;
    int x = warp_incl_scan(v);
    __shared__ int wsum[8];
    if (lane == 31) wsum[wid] = x;
    __syncthreads();
    if (wid == 0) {
        int s = (lane < 8) ? wsum[lane] : 0;
#pragma unroll
        for (int d = 1; d < 8; d <<= 1) {
            int y = __shfl_up_sync(0xffffffffu, s, d);
            if (lane >= d) s += y;
        }
        if (lane < 8) wsum[lane] = s;
    }
    __syncthreads();
    int incl = x + (wid > 0 ? wsum[wid - 1] : 0);
    if (i < N_NODES) g_off[i] = incl - v;
    if (threadIdx.x == 255) g_bsum[blockIdx.x] = incl;
}

__global__ void __launch_bounds__(256) scan_block_kernel() {
    int t = threadIdx.x;
    int v = (t < NBLK) ? g_bsum[t] : 0;
    int lane = t & 31, wid = t >> 5;
    int x = warp_incl_scan(v);
    __shared__ int wsum[8];
    if (lane == 31) wsum[wid] = x;
    __syncthreads();
    if (wid == 0) {
        int s = (lane < 8) ? wsum[lane] : 0;
#pragma unroll
        for (int d = 1; d < 8; d <<= 1) {
            int y = __shfl_up_sync(0xffffffffu, s, d);
            if (lane >= d) s += y;
        }
        if (lane < 8) wsum[lane] = s;
    }
    __syncthreads();
    int incl = x + (wid > 0 ? wsum[wid - 1] : 0);
    if (t < NBLK) g_bpre[t] = incl - v;
}

__global__ void finalize_kernel() {
    int i = blockIdx.x * blockDim.x + threadIdx.x;
    if (i < N_NODES) {
        int off = g_off[i] + g_bpre[i >> 8];
        g_off[i] = off;
        g_cursor[i] = off;
        g_dis[i] = rsqrtf((float)(g_cnt[i] + 1));
    }
    if (i == 0) g_off[N_NODES] = N_EDGES;
}

// ---------------------------------------------------------------------------
// fill CSR buckets; packed metadata {src, cC, cD} per batch (one LDG.128 each
// in the gather).
// ---------------------------------------------------------------------------
__global__ void __launch_bounds__(256)
fill_kernel(const int* __restrict__ ei,
            const float* __restrict__ fdo,
            const float* __restrict__ fluxes) {
    int e = blockIdx.x * blockDim.x + threadIdx.x;
    if (e >= N_EDGES) return;
    int s = load_idx(ei, e);
    int t = load_idx(ei, (size_t)N_EDGES + e);

    int pos = atomicAdd(&g_cursor[t], 1);

    const float f0   = fdo[e];
    const float norm = g_dis[s] * g_dis[t];

    const float k0 = 0.5f * (1.0f + tanh_fast(fluxes[s] * fluxes[t]));
    const float k1 = 0.5f * (1.0f + tanh_fast(fluxes[N_NODES + s] * fluxes[N_NODES + t]));
    const float fb0 = k0 * f0 + (1.0f - k0) * (1.0f - f0);
    const float fb1 = k1 * f0 + (1.0f - k1) * (1.0f - f0);

    const float sb = __int_as_float(s);
    g_em0[pos] = make_float4(sb, norm * (1.0f - fb0), norm * fb0, 0.0f);
    g_em1[pos] = make_float4(sb, norm * (1.0f - fb1), norm * fb1, 0.0f);
}

// ---------------------------------------------------------------------------
// Dual GEMM -> interleaved fp16 rows [xc(64)|xd(64)]. FFMA2-packed.
// ---------------------------------------------------------------------------
__global__ void __launch_bounds__(256)
gemm_kernel(const float* __restrict__ x,
            const float* __restrict__ Wc,
            const float* __restrict__ Wd) {
    const int o  = threadIdx.x >> 2;
    const int kg = threadIdx.x & 3;

    unsigned long long wp[16];
#pragma unroll
    for (int i = 0; i < 16; i++)
        wp[i] = pk2(Wc[o * C + kg * 16 + i], Wd[o * C + kg * 16 + i]);

    __shared__ __align__(16) float xs[4][C];
    const int M = BATCH * N_NODES;
    const int lr = threadIdx.x >> 6;
    const int lc = threadIdx.x & 63;

    for (int m0 = blockIdx.x * 4; m0 < M; m0 += gridDim.x * 4) {
        __syncthreads();
        xs[lr][lc] = x[(size_t)(m0 + lr) * C + lc];
        __syncthreads();

#pragma unroll
        for (int r2 = 0; r2 < 4; r2++) {
            const float4* xp = (const float4*)&xs[r2][kg * 16];
            unsigned long long acc = 0ull;
#pragma unroll
            for (int j = 0; j < 4; j++) {
                float4 xv = xp[j];
                fma2(acc, pk2(xv.x, xv.x), wp[4 * j + 0]);
                fma2(acc, pk2(xv.y, xv.y), wp[4 * j + 1]);
                fma2(acc, pk2(xv.z, xv.z), wp[4 * j + 2]);
                fma2(acc, pk2(xv.w, xv.w), wp[4 * j + 3]);
            }
            float sc, sd;
            upk2(acc, sc, sd);
            sc += __shfl_xor_sync(0xffffffffu, sc, 1);
            sc += __shfl_xor_sync(0xffffffffu, sc, 2);
            sd += __shfl_xor_sync(0xffffffffu, sd, 1);
            sd += __shfl_xor_sync(0xffffffffu, sd, 2);
            float sc2 = __shfl_xor_sync(0xffffffffu, sc, 4);
            float sd2 = __shfl_xor_sync(0xffffffffu, sd, 4);

            if (kg == 0 && (o & 1) == 0) {
                __half* row = g_xi + (size_t)(m0 + r2) * (2 * C);
                *(__half2*)(row + o)     = __floats2half2_rn(sc, sc2);
                *(__half2*)(row + C + o) = __floats2half2_rn(sd, sd2);
            }
        }
    }
}

// ---------------------------------------------------------------------------
// Gather (R5-winning structure): one warp per (node,batch), batch-major.
// Four 8-lane groups, one edge per group per iteration; lane covers 8 channels.
// Packed metadata prefetched one iteration ahead (single LDG.128).
// ---------------------------------------------------------------------------
__global__ void __launch_bounds__(256)
gather_kernel(const float* __restrict__ bias, float* __restrict__ out) {
    const int w = (int)((blockIdx.x * blockDim.x + threadIdx.x) >> 5);
    if (w >= BATCH * N_NODES) return;
    const int b    = (w < N_NODES) ? 0 : 1;
    const int n    = (w < N_NODES) ? w : (w - N_NODES);
    const int lane = threadIdx.x & 31;
    const int g    = lane >> 3;        // edge group 0..3
    const int l8   = lane & 7;         // 8 channels: l8*8 .. +8

    const int beg = g_off[n];
    const int end = g_off[n + 1];

    const __half*  __restrict__ xib = g_xi + (size_t)b * N_NODES * (2 * C);
    const float4*  __restrict__ em  = b ? g_em1 : g_em0;

    unsigned long long a0 = 0ull, a1 = 0ull, a2 = 0ull, a3 = 0ull;

    if (g == 0) {   // self-loop + bias init
        const float dv  = g_dis[n];
        const float nrm = dv * dv;
        const float4 b0 = *(const float4*)(bias + l8 * 8);
        const float4 b1 = *(const float4*)(bias + l8 * 8 + 4);
        const uint4  xh = *(const uint4*)(xib + (size_t)n * (2 * C) + l8 * 8);
        const float2 x0 = __half22float2(*(const __half2*)&xh.x);
        const float2 x1 = __half22float2(*(const __half2*)&xh.y);
        const float2 x2 = __half22float2(*(const __half2*)&xh.z);
        const float2 x3 = __half22float2(*(const __half2*)&xh.w);
        a0 = pk2(fmaf(nrm, x0.x, b0.x), fmaf(nrm, x0.y, b0.y));
        a1 = pk2(fmaf(nrm, x1.x, b0.z), fmaf(nrm, x1.y, b0.w));
        a2 = pk2(fmaf(nrm, x2.x, b1.x), fmaf(nrm, x2.y, b1.y));
        a3 = pk2(fmaf(nrm, x3.x, b1.z), fmaf(nrm, x3.y, b1.w));
    }

    int i = beg + g;
    if (i < end) {
        float4 m = em[i];
        for (; i < end; ) {
            const int inext = i + 4;
            float4 m2 = make_float4(0.f, 0.f, 0.f, 0.f);
            if (inext < end) m2 = em[inext];

            const int s = __float_as_int(m.x);
            const __half* row = xib + (size_t)s * (2 * C) + l8 * 8;
            const uint4 A = *(const uint4*)(row);        // xc: 8 halfs
            const uint4 D = *(const uint4*)(row + C);    // xd: 8 halfs

            const unsigned long long cc = pk2(m.y, m.y);
            const unsigned long long cd = pk2(m.z, m.z);

            float2 t;
            t = __half22float2(*(const __half2*)&A.x); fma2(a0, pk2(t.x, t.y), cc);
            t = __half22float2(*(const __half2*)&A.y); fma2(a1, pk2(t.x, t.y), cc);
            t = __half22float2(*(const __half2*)&A.z); fma2(a2, pk2(t.x, t.y), cc);
            t = __half22float2(*(const __half2*)&A.w); fma2(a3, pk2(t.x, t.y), cc);
            t = __half22float2(*(const __half2*)&D.x); fma2(a0, pk2(t.x, t.y), cd);
            t = __half22float2(*(const __half2*)&D.y); fma2(a1, pk2(t.x, t.y), cd);
            t = __half22float2(*(const __half2*)&D.z); fma2(a2, pk2(t.x, t.y), cd);
            t = __half22float2(*(const __half2*)&D.w); fma2(a3, pk2(t.x, t.y), cd);

            i = inext; m = m2;
        }
    }

    // reduce the 4 groups
    float f0, f1, f2, f3, f4, f5, f6, f7;
    upk2(a0, f0, f1); upk2(a1, f2, f3); upk2(a2, f4, f5); upk2(a3, f6, f7);
#pragma unroll
    for (int d = 8; d <= 16; d <<= 1) {
        f0 += __shfl_xor_sync(0xffffffffu, f0, d);
        f1 += __shfl_xor_sync(0xffffffffu, f1, d);
        f2 += __shfl_xor_sync(0xffffffffu, f2, d);
        f3 += __shfl_xor_sync(0xffffffffu, f3, d);
        f4 += __shfl_xor_sync(0xffffffffu, f4, d);
        f5 += __shfl_xor_sync(0xffffffffu, f5, d);
        f6 += __shfl_xor_sync(0xffffffffu, f6, d);
        f7 += __shfl_xor_sync(0xffffffffu, f7, d);
    }

    if (g == 0) {
        float* orow = out + ((size_t)b * N_NODES + n) * C + l8 * 8;
        *(float4*)(orow)     = make_float4(f0, f1, f2, f3);
        *(float4*)(orow + 4) = make_float4(f4, f5, f6, f7);
    }
}

// ---------------------------------------------------------------------------
extern "C" void kernel_launch(void* const* d_in, const int* in_sizes, int n_in,
                              void* d_out, int out_size) {
    const float* x    = (const float*)d_in[0];
    const int*   ei   = (const int*)d_in[1];
    const float* fdo  = (const float*)d_in[2];
    const float* flux = (const float*)d_in[3];
    const float* Wc   = (const float*)d_in[4];
    const float* Wd   = (const float*)d_in[5];
    const float* bias = (const float*)d_in[6];
    float* out = (float*)d_out;

    static cudaStream_t s2 = nullptr;
    static cudaEvent_t evFork = nullptr, evJoin = nullptr;
    if (!s2) {
        cudaStreamCreateWithFlags(&s2, cudaStreamNonBlocking);
        cudaEventCreateWithFlags(&evFork, cudaEventDisableTiming);
        cudaEventCreateWithFlags(&evJoin, cudaEventDisableTiming);
    }

    cudaEventRecord(evFork, 0);
    cudaStreamWaitEvent(s2, evFork, 0);
    gemm_kernel<<<2960, 256, 0, s2>>>(x, Wc, Wd);
    cudaEventRecord(evJoin, s2);

    detect_zero_kernel<<<NBLK, 256>>>((const unsigned int*)ei);
    hist_kernel<<<(N_EDGES / 2 + 255) / 256, 256>>>(ei);
    scan_local_kernel<<<NBLK, 256>>>();
    scan_block_kernel<<<1, 256>>>();
    finalize_kernel<<<NBLK, 256>>>();
    fill_kernel<<<(N_EDGES + 255) / 256, 256>>>(ei, fdo, flux);

    cudaStreamWaitEvent(0, evJoin, 0);
    gather_kernel<<<(BATCH * N_NODES * 32 + 255) / 256, 256>>>(bias, out);
}

// round 8
// speedup vs baseline: 1.2913x; 1.0644x over previous
#include <cuda_runtime.h>
#include <cuda_fp16.h>
#include <math.h>

#define N_NODES 50000
#define N_EDGES 1600000
#define BATCH   2
#define C       64
#define NBLK    ((N_NODES + 255) / 256)

// ---- scratch ----
__device__ int    g_cnt[N_NODES];
__device__ int    g_off[N_NODES + 1];
__device__ int    g_cursor[N_NODES];
__device__ int    g_bsum[NBLK];
__device__ int    g_bpre[NBLK];
__device__ float  g_dis[N_NODES];
// interleaved per (batch,node) row: [xc: 64 halfs][xd: 64 halfs] = 256 B
__device__ __align__(16) __half g_xi[(size_t)BATCH * N_NODES * 2 * C];
// packed edge metadata per batch: {src(int bits), cC, cD, unused}
__device__ float4 g_em0[N_EDGES];
__device__ float4 g_em1[N_EDGES];
__device__ int    g_is64;

// ---- packed f32x2 helpers ----
__device__ __forceinline__ unsigned long long pk2(float x, float y) {
    unsigned long long r;
    asm("mov.b64 %0, {%1,%2};" : "=l"(r) : "f"(x), "f"(y));
    return r;
}
__device__ __forceinline__ void upk2(unsigned long long v, float& x, float& y) {
    asm("mov.b64 {%0,%1}, %2;" : "=f"(x), "=f"(y) : "l"(v));
}
__device__ __forceinline__ void fma2(unsigned long long& c,
                                     unsigned long long a,
                                     unsigned long long b) {
    asm("fma.rn.f32x2 %0, %1, %2, %0;" : "+l"(c) : "l"(a), "l"(b));
}
__device__ __forceinline__ float tanh_fast(float x) {
    asm("tanh.approx.f32 %0, %0;" : "+f"(x));
    return x;
}

// ---------------------------------------------------------------------------
__global__ void detect_zero_kernel(const unsigned int* __restrict__ w) {
    int i = blockIdx.x * blockDim.x + threadIdx.x;
    if (i < N_NODES) g_cnt[i] = 0;
    if (blockIdx.x == 0) {
        __shared__ unsigned int acc;
        if (threadIdx.x == 0) acc = 0u;
        __syncthreads();
        unsigned int v = 0u;
        for (int j = threadIdx.x; j < 4096; j += blockDim.x)
            v |= w[(size_t)2 * j * 97 + 1];
        atomicOr(&acc, v);
        __syncthreads();
        if (threadIdx.x == 0) g_is64 = (acc == 0u) ? 1 : 0;
    }
}

__device__ __forceinline__ int load_idx(const int* __restrict__ ei, size_t e) {
    return g_is64 ? ei[2 * e] : ei[e];
}

__global__ void hist_kernel(const int* __restrict__ ei) {
    int e2 = (blockIdx.x * blockDim.x + threadIdx.x) * 2;
    if (e2 >= N_EDGES) return;
    int t0, t1;
    if (g_is64) {
        const int4 v = *(const int4*)(ei + 2 * ((size_t)N_EDGES + e2));
        t0 = v.x; t1 = v.z;
    } else {
        const int2 v = *(const int2*)(ei + (size_t)N_EDGES + e2);
        t0 = v.x; t1 = v.y;
    }
    atomicAdd(&g_cnt[t0], 1);
    atomicAdd(&g_cnt[t1], 1);
}

// ---------------------------------------------------------------------------
__device__ __forceinline__ int warp_incl_scan(int x) {
#pragma unroll
    for (int d = 1; d < 32; d <<= 1) {
        int y = __shfl_up_sync(0xffffffffu, x, d);
        if ((threadIdx.x & 31) >= d) x += y;
    }
    return x;
}

__global__ void __launch_bounds__(256) scan_local_kernel() {
    int i = blockIdx.x * 256 + threadIdx.x;
    int v = (i < N_NODES) ? g_cnt[i] : 0;
    int lane = threadIdx.x & 31, wid = threadIdx.x >> 5;
    int x = warp_incl_scan(v);
    __shared__ int wsum[8];
    if (lane == 31) wsum[wid] = x;
    __syncthreads();
    if (wid == 0) {
        int s = (lane < 8) ? wsum[lane] : 0;
#pragma unroll
        for (int d = 1; d < 8; d <<= 1) {
            int y = __shfl_up_sync(0xffffffffu, s, d);
            if (lane >= d) s += y;
        }
        if (lane < 8) wsum[lane] = s;
    }
    __syncthreads();
    int incl = x + (wid > 0 ? wsum[wid - 1] : 0);
    if (i < N_NODES) g_off[i] = incl - v;
    if (threadIdx.x == 255) g_bsum[blockIdx.x] = incl;
}

__global__ void __launch_bounds__(256) scan_block_kernel() {
    int t = threadIdx.x;
    int v = (t < NBLK) ? g_bsum[t] : 0;
    int lane = t & 31, wid = t >> 5;
    int x = warp_incl_scan(v);
    __shared__ int wsum[8];
    if (lane == 31) wsum[wid] = x;
    __syncthreads();
    if (wid == 0) {
        int s = (lane < 8) ? wsum[lane] : 0;
#pragma unroll
        for (int d = 1; d < 8; d <<= 1) {
            int y = __shfl_up_sync(0xffffffffu, s, d);
            if (lane >= d) s += y;
        }
        if (lane < 8) wsum[lane] = s;
    }
    __syncthreads();
    int incl = x + (wid > 0 ? wsum[wid - 1] : 0);
    if (t < NBLK) g_bpre[t] = incl - v;
}

__global__ void finalize_kernel() {
    int i = blockIdx.x * blockDim.x + threadIdx.x;
    if (i < N_NODES) {
        int off = g_off[i] + g_bpre[i >> 8];
        g_off[i] = off;
        g_cursor[i] = off;
        g_dis[i] = rsqrtf((float)(g_cnt[i] + 1));
    }
    if (i == 0) g_off[N_NODES] = N_EDGES;
}

// ---------------------------------------------------------------------------
__global__ void __launch_bounds__(256)
fill_kernel(const int* __restrict__ ei,
            const float* __restrict__ fdo,
            const float* __restrict__ fluxes) {
    int e = blockIdx.x * blockDim.x + threadIdx.x;
    if (e >= N_EDGES) return;
    int s = load_idx(ei, e);
    int t = load_idx(ei, (size_t)N_EDGES + e);

    int pos = atomicAdd(&g_cursor[t], 1);

    const float f0   = fdo[e];
    const float norm = g_dis[s] * g_dis[t];

    const float k0 = 0.5f * (1.0f + tanh_fast(fluxes[s] * fluxes[t]));
    const float k1 = 0.5f * (1.0f + tanh_fast(fluxes[N_NODES + s] * fluxes[N_NODES + t]));
    const float fb0 = k0 * f0 + (1.0f - k0) * (1.0f - f0);
    const float fb1 = k1 * f0 + (1.0f - k1) * (1.0f - f0);

    const float sb = __int_as_float(s);
    g_em0[pos] = make_float4(sb, norm * (1.0f - fb0), norm * fb0, 0.0f);
    g_em1[pos] = make_float4(sb, norm * (1.0f - fb1), norm * fb1, 0.0f);
}

// ---------------------------------------------------------------------------
// Dual GEMM -> interleaved fp16 rows [xc(64)|xd(64)]. FFMA2-packed.
// ---------------------------------------------------------------------------
__global__ void __launch_bounds__(256)
gemm_kernel(const float* __restrict__ x,
            const float* __restrict__ Wc,
            const float* __restrict__ Wd) {
    const int o  = threadIdx.x >> 2;
    const int kg = threadIdx.x & 3;

    unsigned long long wp[16];
#pragma unroll
    for (int i = 0; i < 16; i++)
        wp[i] = pk2(Wc[o * C + kg * 16 + i], Wd[o * C + kg * 16 + i]);

    __shared__ __align__(16) float xs[4][C];
    const int M = BATCH * N_NODES;
    const int lr = threadIdx.x >> 6;
    const int lc = threadIdx.x & 63;

    for (int m0 = blockIdx.x * 4; m0 < M; m0 += gridDim.x * 4) {
        __syncthreads();
        xs[lr][lc] = x[(size_t)(m0 + lr) * C + lc];
        __syncthreads();

#pragma unroll
        for (int r2 = 0; r2 < 4; r2++) {
            const float4* xp = (const float4*)&xs[r2][kg * 16];
            unsigned long long acc = 0ull;
#pragma unroll
            for (int j = 0; j < 4; j++) {
                float4 xv = xp[j];
                fma2(acc, pk2(xv.x, xv.x), wp[4 * j + 0]);
                fma2(acc, pk2(xv.y, xv.y), wp[4 * j + 1]);
                fma2(acc, pk2(xv.z, xv.z), wp[4 * j + 2]);
                fma2(acc, pk2(xv.w, xv.w), wp[4 * j + 3]);
            }
            float sc, sd;
            upk2(acc, sc, sd);
            sc += __shfl_xor_sync(0xffffffffu, sc, 1);
            sc += __shfl_xor_sync(0xffffffffu, sc, 2);
            sd += __shfl_xor_sync(0xffffffffu, sd, 1);
            sd += __shfl_xor_sync(0xffffffffu, sd, 2);
            float sc2 = __shfl_xor_sync(0xffffffffu, sc, 4);
            float sd2 = __shfl_xor_sync(0xffffffffu, sd, 4);

            if (kg == 0 && (o & 1) == 0) {
                __half* row = g_xi + (size_t)(m0 + r2) * (2 * C);
                *(__half2*)(row + o)     = __floats2half2_rn(sc, sc2);
                *(__half2*)(row + C + o) = __floats2half2_rn(sd, sd2);
            }
        }
    }
}

// ---------------------------------------------------------------------------
// Gather: one warp per (node,batch), batch-major. Four 8-lane groups; each
// group processes 4 edges per loop trip with ALL 8 row LDG.128s issued before
// any FMA (deep MLP). Branch-free tail: index clamp + coefficient zeroing.
// ---------------------------------------------------------------------------
__device__ __forceinline__ void edge_fma(unsigned long long& a0, unsigned long long& a1,
                                         unsigned long long& a2, unsigned long long& a3,
                                         uint4 A, uint4 D, float cC, float cD) {
    const unsigned long long cc = pk2(cC, cC);
    const unsigned long long cd = pk2(cD, cD);
    float2 t;
    t = __half22float2(*(const __half2*)&A.x); fma2(a0, pk2(t.x, t.y), cc);
    t = __half22float2(*(const __half2*)&A.y); fma2(a1, pk2(t.x, t.y), cc);
    t = __half22float2(*(const __half2*)&A.z); fma2(a2, pk2(t.x, t.y), cc);
    t = __half22float2(*(const __half2*)&A.w); fma2(a3, pk2(t.x, t.y), cc);
    t = __half22float2(*(const __half2*)&D.x); fma2(a0, pk2(t.x, t.y), cd);
    t = __half22float2(*(const __half2*)&D.y); fma2(a1, pk2(t.x, t.y), cd);
    t = __half22float2(*(const __half2*)&D.z); fma2(a2, pk2(t.x, t.y), cd);
    t = __half22float2(*(const __half2*)&D.w); fma2(a3, pk2(t.x, t.y), cd);
}

__global__ void __launch_bounds__(256)
gather_kernel(const float* __restrict__ bias, float* __restrict__ out) {
    const int w = (int)((blockIdx.x * blockDim.x + threadIdx.x) >> 5);
    if (w >= BATCH * N_NODES) return;
    const int b    = (w < N_NODES) ? 0 : 1;
    const int n    = (w < N_NODES) ? w : (w - N_NODES);
    const int lane = threadIdx.x & 31;
    const int g    = lane >> 3;        // edge group 0..3
    const int l8   = lane & 7;         // 8 channels: l8*8 .. +8

    const int beg = g_off[n];
    const int end = g_off[n + 1];

    const __half*  __restrict__ xib = g_xi + (size_t)b * N_NODES * (2 * C);
    const float4*  __restrict__ em  = b ? g_em1 : g_em0;

    unsigned long long a0 = 0ull, a1 = 0ull, a2 = 0ull, a3 = 0ull;

    if (g == 0) {   // self-loop + bias init
        const float dv  = g_dis[n];
        const float nrm = dv * dv;
        const float4 b0 = *(const float4*)(bias + l8 * 8);
        const float4 b1 = *(const float4*)(bias + l8 * 8 + 4);
        const uint4  xh = *(const uint4*)(xib + (size_t)n * (2 * C) + l8 * 8);
        const float2 x0 = __half22float2(*(const __half2*)&xh.x);
        const float2 x1 = __half22float2(*(const __half2*)&xh.y);
        const float2 x2 = __half22float2(*(const __half2*)&xh.z);
        const float2 x3 = __half22float2(*(const __half2*)&xh.w);
        a0 = pk2(fmaf(nrm, x0.x, b0.x), fmaf(nrm, x0.y, b0.y));
        a1 = pk2(fmaf(nrm, x1.x, b0.z), fmaf(nrm, x1.y, b0.w));
        a2 = pk2(fmaf(nrm, x2.x, b1.x), fmaf(nrm, x2.y, b1.y));
        a3 = pk2(fmaf(nrm, x3.x, b1.z), fmaf(nrm, x3.y, b1.w));
    }

    int i = beg + g;                   // this group's slots: i, i+4, i+8, i+12
    if (i < end) {
        const int last = end - 1;
        float4 m[4];
#pragma unroll
        for (int k = 0; k < 4; k++) {
            const int  j = i + 4 * k;
            const bool v = (j < end);
            const float4 t = __ldg(&em[v ? j : last]);
            m[k] = make_float4(t.x, v ? t.y : 0.0f, v ? t.z : 0.0f, 0.0f);
        }

        for (;;) {
            // 1) issue all 8 row loads (max lines in flight)
            uint4 A[4], D[4];
#pragma unroll
            for (int k = 0; k < 4; k++) {
                const __half* row = xib +
                    (size_t)__float_as_int(m[k].x) * (2 * C) + l8 * 8;
                A[k] = __ldg((const uint4*)(row));
                D[k] = __ldg((const uint4*)(row + C));
            }

            // 2) prefetch next 4 metas (clamped; harmless when exiting)
            i += 16;
            const bool more = (i < end);
            float4 mn[4];
#pragma unroll
            for (int k = 0; k < 4; k++) {
                const int  j = i + 4 * k;
                const bool v = (j < end);
                const float4 t = __ldg(&em[v ? j : last]);
                mn[k] = make_float4(t.x, v ? t.y : 0.0f, v ? t.z : 0.0f, 0.0f);
            }

            // 3) consume
#pragma unroll
            for (int k = 0; k < 4; k++)
                edge_fma(a0, a1, a2, a3, A[k], D[k], m[k].y, m[k].z);

            if (!more) break;
#pragma unroll
            for (int k = 0; k < 4; k++) m[k] = mn[k];
        }
    }

    // reduce the 4 groups
    float f0, f1, f2, f3, f4, f5, f6, f7;
    upk2(a0, f0, f1); upk2(a1, f2, f3); upk2(a2, f4, f5); upk2(a3, f6, f7);
#pragma unroll
    for (int d = 8; d <= 16; d <<= 1) {
        f0 += __shfl_xor_sync(0xffffffffu, f0, d);
        f1 += __shfl_xor_sync(0xffffffffu, f1, d);
        f2 += __shfl_xor_sync(0xffffffffu, f2, d);
        f3 += __shfl_xor_sync(0xffffffffu, f3, d);
        f4 += __shfl_xor_sync(0xffffffffu, f4, d);
        f5 += __shfl_xor_sync(0xffffffffu, f5, d);
        f6 += __shfl_xor_sync(0xffffffffu, f6, d);
        f7 += __shfl_xor_sync(0xffffffffu, f7, d);
    }

    if (g == 0) {
        float* orow = out + ((size_t)b * N_NODES + n) * C + l8 * 8;
        *(float4*)(orow)     = make_float4(f0, f1, f2, f3);
        *(float4*)(orow + 4) = make_float4(f4, f5, f6, f7);
    }
}

// ---------------------------------------------------------------------------
extern "C" void kernel_launch(void* const* d_in, const int* in_sizes, int n_in,
                              void* d_out, int out_size) {
    const float* x    = (const float*)d_in[0];
    const int*   ei   = (const int*)d_in[1];
    const float* fdo  = (const float*)d_in[2];
    const float* flux = (const float*)d_in[3];
    const float* Wc   = (const float*)d_in[4];
    const float* Wd   = (const float*)d_in[5];
    const float* bias = (const float*)d_in[6];
    float* out = (float*)d_out;

    static cudaStream_t s2 = nullptr;
    static cudaEvent_t evFork = nullptr, evJoin = nullptr;
    if (!s2) {
        cudaStreamCreateWithFlags(&s2, cudaStreamNonBlocking);
        cudaEventCreateWithFlags(&evFork, cudaEventDisableTiming);
        cudaEventCreateWithFlags(&evJoin, cudaEventDisableTiming);
    }

    cudaEventRecord(evFork, 0);
    cudaStreamWaitEvent(s2, evFork, 0);
    gemm_kernel<<<2960, 256, 0, s2>>>(x, Wc, Wd);
    cudaEventRecord(evJoin, s2);

    detect_zero_kernel<<<NBLK, 256>>>((const unsigned int*)ei);
    hist_kernel<<<(N_EDGES / 2 + 255) / 256, 256>>>(ei);
    scan_local_kernel<<<NBLK, 256>>>();
    scan_block_kernel<<<1, 256>>>();
    finalize_kernel<<<NBLK, 256>>>();
    fill_kernel<<<(N_EDGES + 255) / 256, 256>>>(ei, fdo, flux);

    cudaStreamWaitEvent(0, evJoin, 0);
    gather_kernel<<<(BATCH * N_NODES * 32 + 255) / 256, 256>>>(bias, out);
}

// round 9
// speedup vs baseline: 1.4025x; 1.0861x over previous
#include <cuda_runtime.h>
#include <cuda_fp16.h>
#include <math.h>

#define N_NODES 50000
#define N_EDGES 1600000
#define BATCH   2
#define C       64
#define NBLK    ((N_NODES + 255) / 256)

// ---- scratch ----
__device__ int    g_cnt[N_NODES];
__device__ int    g_off[N_NODES + 1];
__device__ int    g_cursor[N_NODES];
__device__ int    g_bsum[NBLK];
__device__ int    g_bpre[NBLK];
__device__ float4 g_ni[N_NODES];      // {flux_b0, flux_b1, dis, 0}
// interleaved per (batch,node) row: [xc: 64 halfs][xd: 64 halfs] = 256 B
__device__ __align__(16) __half g_xi[(size_t)BATCH * N_NODES * 2 * C];
// packed edge metadata per batch: {src(int bits), cC, cD, unused} (16 B)
__device__ float4 g_em0[N_EDGES];
__device__ float4 g_em1[N_EDGES];
__device__ int    g_is64;

// ---- packed f32x2 helpers ----
__device__ __forceinline__ unsigned long long pk2(float x, float y) {
    unsigned long long r;
    asm("mov.b64 %0, {%1,%2};" : "=l"(r) : "f"(x), "f"(y));
    return r;
}
__device__ __forceinline__ void upk2(unsigned long long v, float& x, float& y) {
    asm("mov.b64 {%0,%1}, %2;" : "=f"(x), "=f"(y) : "l"(v));
}
__device__ __forceinline__ void fma2(unsigned long long& c,
                                     unsigned long long a,
                                     unsigned long long b) {
    asm("fma.rn.f32x2 %0, %1, %2, %0;" : "+l"(c) : "l"(a), "l"(b));
}
__device__ __forceinline__ void add2(unsigned long long& c, unsigned long long a) {
    asm("add.rn.f32x2 %0, %0, %1;" : "+l"(c) : "l"(a));
}
__device__ __forceinline__ float tanh_fast(float x) {
    asm("tanh.approx.f32 %0, %0;" : "+f"(x));
    return x;
}

// ---------------------------------------------------------------------------
__global__ void detect_zero_kernel(const unsigned int* __restrict__ w) {
    int i = blockIdx.x * blockDim.x + threadIdx.x;
    if (i < N_NODES) g_cnt[i] = 0;
    if (blockIdx.x == 0) {
        __shared__ unsigned int acc;
        if (threadIdx.x == 0) acc = 0u;
        __syncthreads();
        unsigned int v = 0u;
        for (int j = threadIdx.x; j < 4096; j += blockDim.x)
            v |= w[(size_t)2 * j * 97 + 1];
        atomicOr(&acc, v);
        __syncthreads();
        if (threadIdx.x == 0) g_is64 = (acc == 0u) ? 1 : 0;
    }
}

__device__ __forceinline__ int load_idx(const int* __restrict__ ei, size_t e) {
    return g_is64 ? ei[2 * e] : ei[e];
}

__global__ void hist_kernel(const int* __restrict__ ei) {
    int e2 = (blockIdx.x * blockDim.x + threadIdx.x) * 2;
    if (e2 >= N_EDGES) return;
    int t0, t1;
    if (g_is64) {
        const int4 v = *(const int4*)(ei + 2 * ((size_t)N_EDGES + e2));
        t0 = v.x; t1 = v.z;
    } else {
        const int2 v = *(const int2*)(ei + (size_t)N_EDGES + e2);
        t0 = v.x; t1 = v.y;
    }
    atomicAdd(&g_cnt[t0], 1);
    atomicAdd(&g_cnt[t1], 1);
}

// ---------------------------------------------------------------------------
__device__ __forceinline__ int warp_incl_scan(int x) {
#pragma unroll
    for (int d = 1; d < 32; d <<= 1) {
        int y = __shfl_up_sync(0xffffffffu, x, d);
        if ((threadIdx.x & 31) >= d) x += y;
    }
    return x;
}

__global__ void __launch_bounds__(256) scan_local_kernel() {
    int i = blockIdx.x * 256 + threadIdx.x;
    int v = (i < N_NODES) ? g_cnt[i] : 0;
    int lane = threadIdx.x & 31, wid = threadIdx.x >> 5;
    int x = warp_incl_scan(v);
    __shared__ int wsum[8];
    if (lane == 31) wsum[wid] = x;
    __syncthreads();
    if (wid == 0) {
        int s = (lane < 8) ? wsum[lane] : 0;
#pragma unroll
        for (int d = 1; d < 8; d <<= 1) {
            int y = __shfl_up_sync(0xffffffffu, s, d);
            if (lane >= d) s += y;
        }
        if (lane < 8) wsum[lane] = s;
    }
    __syncthreads();
    int incl = x + (wid > 0 ? wsum[wid - 1] : 0);
    if (i < N_NODES) g_off[i] = incl - v;
    if (threadIdx.x == 255) g_bsum[blockIdx.x] = incl;
}

__global__ void __launch_bounds__(256) scan_block_kernel() {
    int t = threadIdx.x;
    int v = (t < NBLK) ? g_bsum[t] : 0;
    int lane = t & 31, wid = t >> 5;
    int x = warp_incl_scan(v);
    __shared__ int wsum[8];
    if (lane == 31) wsum[wid] = x;
    __syncthreads();
    if (wid == 0) {
        int s = (lane < 8) ? wsum[lane] : 0;
#pragma unroll
        for (int d = 1; d < 8; d <<= 1) {
            int y = __shfl_up_sync(0xffffffffu, s, d);
            if (lane >= d) s += y;
        }
        if (lane < 8) wsum[lane] = s;
    }
    __syncthreads();
    int incl = x + (wid > 0 ? wsum[wid - 1] : 0);
    if (t < NBLK) g_bpre[t] = incl - v;
}

__global__ void finalize_kernel(const float* __restrict__ fluxes) {
    int i = blockIdx.x * blockDim.x + threadIdx.x;
    if (i < N_NODES) {
        int off = g_off[i] + g_bpre[i >> 8];
        g_off[i] = off;
        g_cursor[i] = off;
        const float dis = rsqrtf((float)(g_cnt[i] + 1));
        g_ni[i] = make_float4(fluxes[i], fluxes[N_NODES + i], dis, 0.0f);
    }
    if (i == 0) g_off[N_NODES] = N_EDGES;
}

// ---------------------------------------------------------------------------
// fill CSR buckets; node info gathered as 2 x 16B (one sector each).
// ---------------------------------------------------------------------------
__global__ void __launch_bounds__(256)
fill_kernel(const int* __restrict__ ei,
            const float* __restrict__ fdo) {
    int e = blockIdx.x * blockDim.x + threadIdx.x;
    if (e >= N_EDGES) return;
    int s = load_idx(ei, e);
    int t = load_idx(ei, (size_t)N_EDGES + e);

    int pos = atomicAdd(&g_cursor[t], 1);

    const float4 nis = __ldg(&g_ni[s]);
    const float4 nit = __ldg(&g_ni[t]);

    const float f0   = fdo[e];
    const float norm = nis.z * nit.z;

    const float k0 = 0.5f * (1.0f + tanh_fast(nis.x * nit.x));
    const float k1 = 0.5f * (1.0f + tanh_fast(nis.y * nit.y));
    const float fb0 = k0 * f0 + (1.0f - k0) * (1.0f - f0);
    const float fb1 = k1 * f0 + (1.0f - k1) * (1.0f - f0);

    const float sb = __int_as_float(s);
    g_em0[pos] = make_float4(sb, norm * (1.0f - fb0), norm * fb0, 0.0f);
    g_em1[pos] = make_float4(sb, norm * (1.0f - fb1), norm * fb1, 0.0f);
}

// ---------------------------------------------------------------------------
// Dual GEMM -> interleaved fp16 rows [xc(64)|xd(64)]. FFMA2-packed.
// ---------------------------------------------------------------------------
__global__ void __launch_bounds__(256)
gemm_kernel(const float* __restrict__ x,
            const float* __restrict__ Wc,
            const float* __restrict__ Wd) {
    const int o  = threadIdx.x >> 2;
    const int kg = threadIdx.x & 3;

    unsigned long long wp[16];
#pragma unroll
    for (int i = 0; i < 16; i++)
        wp[i] = pk2(Wc[o * C + kg * 16 + i], Wd[o * C + kg * 16 + i]);

    __shared__ __align__(16) float xs[4][C];
    const int M = BATCH * N_NODES;
    const int lr = threadIdx.x >> 6;
    const int lc = threadIdx.x & 63;

    for (int m0 = blockIdx.x * 4; m0 < M; m0 += gridDim.x * 4) {
        __syncthreads();
        xs[lr][lc] = x[(size_t)(m0 + lr) * C + lc];
        __syncthreads();

#pragma unroll
        for (int r2 = 0; r2 < 4; r2++) {
            const float4* xp = (const float4*)&xs[r2][kg * 16];
            unsigned long long acc = 0ull;
#pragma unroll
            for (int j = 0; j < 4; j++) {
                float4 xv = xp[j];
                fma2(acc, pk2(xv.x, xv.x), wp[4 * j + 0]);
                fma2(acc, pk2(xv.y, xv.y), wp[4 * j + 1]);
                fma2(acc, pk2(xv.z, xv.z), wp[4 * j + 2]);
                fma2(acc, pk2(xv.w, xv.w), wp[4 * j + 3]);
            }
            float sc, sd;
            upk2(acc, sc, sd);
            sc += __shfl_xor_sync(0xffffffffu, sc, 1);
            sc += __shfl_xor_sync(0xffffffffu, sc, 2);
            sd += __shfl_xor_sync(0xffffffffu, sd, 1);
            sd += __shfl_xor_sync(0xffffffffu, sd, 2);
            float sc2 = __shfl_xor_sync(0xffffffffu, sc, 4);
            float sd2 = __shfl_xor_sync(0xffffffffu, sd, 4);

            if (kg == 0 && (o & 1) == 0) {
                __half* row = g_xi + (size_t)(m0 + r2) * (2 * C);
                *(__half2*)(row + o)     = __floats2half2_rn(sc, sc2);
                *(__half2*)(row + C + o) = __floats2half2_rn(sd, sd2);
            }
        }
    }
}

// ---------------------------------------------------------------------------
// Gather: one warp per (node,batch), batch-major. Four 8-lane groups; 4 edges
// per trip, all 8 row LDG.128s issued up front. Core math in fp16 (HMUL2 /
// HFMA2), flushed to fp32 pair-accumulators every 2 edges. Branch-free tail
// via index clamp + coefficient zeroing.
// ---------------------------------------------------------------------------
__global__ void __launch_bounds__(256)
gather_kernel(const float* __restrict__ bias, float* __restrict__ out) {
    const int w = (int)((blockIdx.x * blockDim.x + threadIdx.x) >> 5);
    if (w >= BATCH * N_NODES) return;
    const int b    = (w < N_NODES) ? 0 : 1;
    const int n    = (w < N_NODES) ? w : (w - N_NODES);
    const int lane = threadIdx.x & 31;
    const int g    = lane >> 3;        // edge group 0..3
    const int l8   = lane & 7;         // 8 channels: l8*8 .. +8

    const int beg = g_off[n];
    const int end = g_off[n + 1];

    const __half*  __restrict__ xib = g_xi + (size_t)b * N_NODES * (2 * C);
    const float4*  __restrict__ em  = b ? g_em1 : g_em0;

    unsigned long long a0 = 0ull, a1 = 0ull, a2 = 0ull, a3 = 0ull;

    if (g == 0) {   // self-loop + bias init
        const float4 ni = g_ni[n];
        const float nrm = ni.z * ni.z;
        const float4 b0 = *(const float4*)(bias + l8 * 8);
        const float4 b1 = *(const float4*)(bias + l8 * 8 + 4);
        const uint4  xh = *(const uint4*)(xib + (size_t)n * (2 * C) + l8 * 8);
        const float2 x0 = __half22float2(*(const __half2*)&xh.x);
        const float2 x1 = __half22float2(*(const __half2*)&xh.y);
        const float2 x2 = __half22float2(*(const __half2*)&xh.z);
        const float2 x3 = __half22float2(*(const __half2*)&xh.w);
        a0 = pk2(fmaf(nrm, x0.x, b0.x), fmaf(nrm, x0.y, b0.y));
        a1 = pk2(fmaf(nrm, x1.x, b0.z), fmaf(nrm, x1.y, b0.w));
        a2 = pk2(fmaf(nrm, x2.x, b1.x), fmaf(nrm, x2.y, b1.y));
        a3 = pk2(fmaf(nrm, x3.x, b1.z), fmaf(nrm, x3.y, b1.w));
    }

    int i = beg + g;                   // this group's slots: i, i+4, i+8, i+12
    if (i < end) {
        const int last = end - 1;
        float4 m[4];
#pragma unroll
        for (int k = 0; k < 4; k++) {
            const int  j = i + 4 * k;
            const bool v = (j < end);
            const float4 t = __ldg(&em[v ? j : last]);
            m[k] = make_float4(t.x, v ? t.y : 0.0f, v ? t.z : 0.0f, 0.0f);
        }

        for (;;) {
            // 1) issue all 8 row loads (max lines in flight)
            uint4 A[4], D[4];
#pragma unroll
            for (int k = 0; k < 4; k++) {
                const __half* row = xib +
                    (size_t)__float_as_int(m[k].x) * (2 * C) + l8 * 8;
                A[k] = __ldg((const uint4*)(row));
                D[k] = __ldg((const uint4*)(row + C));
            }

            // 2) prefetch next 4 metas (clamped; harmless when exiting)
            i += 16;
            const bool more = (i < end);
            float4 mn[4];
#pragma unroll
            for (int k = 0; k < 4; k++) {
                const int  j = i + 4 * k;
                const bool v = (j < end);
                const float4 t = __ldg(&em[v ? j : last]);
                mn[k] = make_float4(t.x, v ? t.y : 0.0f, v ? t.z : 0.0f, 0.0f);
            }

            // 3) consume: fp16 core, flush every 2 edges
#pragma unroll
            for (int p = 0; p < 2; p++) {
                const int k0 = 2 * p, k1 = 2 * p + 1;
                const __half2 cc0 = __float2half2_rn(m[k0].y);
                const __half2 cd0 = __float2half2_rn(m[k0].z);
                const __half2 cc1 = __float2half2_rn(m[k1].y);
                const __half2 cd1 = __float2half2_rn(m[k1].z);
                const __half2* A0 = (const __half2*)&A[k0];
                const __half2* D0 = (const __half2*)&D[k0];
                const __half2* A1 = (const __half2*)&A[k1];
                const __half2* D1 = (const __half2*)&D[k1];

                __half2 h0 = __hmul2(A0[0], cc0);
                __half2 h1 = __hmul2(A0[1], cc0);
                __half2 h2 = __hmul2(A0[2], cc0);
                __half2 h3 = __hmul2(A0[3], cc0);
                h0 = __hfma2(D0[0], cd0, h0);
                h1 = __hfma2(D0[1], cd0, h1);
                h2 = __hfma2(D0[2], cd0, h2);
                h3 = __hfma2(D0[3], cd0, h3);
                h0 = __hfma2(A1[0], cc1, h0);
                h1 = __hfma2(A1[1], cc1, h1);
                h2 = __hfma2(A1[2], cc1, h2);
                h3 = __hfma2(A1[3], cc1, h3);
                h0 = __hfma2(D1[0], cd1, h0);
                h1 = __hfma2(D1[1], cd1, h1);
                h2 = __hfma2(D1[2], cd1, h2);
                h3 = __hfma2(D1[3], cd1, h3);

                float2 f;
                f = __half22float2(h0); add2(a0, pk2(f.x, f.y));
                f = __half22float2(h1); add2(a1, pk2(f.x, f.y));
                f = __half22float2(h2); add2(a2, pk2(f.x, f.y));
                f = __half22float2(h3); add2(a3, pk2(f.x, f.y));
            }

            if (!more) break;
#pragma unroll
            for (int k = 0; k < 4; k++) m[k] = mn[k];
        }
    }

    // reduce the 4 groups
    float f0, f1, f2, f3, f4, f5, f6, f7;
    upk2(a0, f0, f1); upk2(a1, f2, f3); upk2(a2, f4, f5); upk2(a3, f6, f7);
#pragma unroll
    for (int d = 8; d <= 16; d <<= 1) {
        f0 += __shfl_xor_sync(0xffffffffu, f0, d);
        f1 += __shfl_xor_sync(0xffffffffu, f1, d);
        f2 += __shfl_xor_sync(0xffffffffu, f2, d);
        f3 += __shfl_xor_sync(0xffffffffu, f3, d);
        f4 += __shfl_xor_sync(0xffffffffu, f4, d);
        f5 += __shfl_xor_sync(0xffffffffu, f5, d);
        f6 += __shfl_xor_sync(0xffffffffu, f6, d);
        f7 += __shfl_xor_sync(0xffffffffu, f7, d);
    }

    if (g == 0) {
        float* orow = out + ((size_t)b * N_NODES + n) * C + l8 * 8;
        *(float4*)(orow)     = make_float4(f0, f1, f2, f3);
        *(float4*)(orow + 4) = make_float4(f4, f5, f6, f7);
    }
}

// ---------------------------------------------------------------------------
extern "C" void kernel_launch(void* const* d_in, const int* in_sizes, int n_in,
                              void* d_out, int out_size) {
    const float* x    = (const float*)d_in[0];
    const int*   ei   = (const int*)d_in[1];
    const float* fdo  = (const float*)d_in[2];
    const float* flux = (const float*)d_in[3];
    const float* Wc   = (const float*)d_in[4];
    const float* Wd   = (const float*)d_in[5];
    const float* bias = (const float*)d_in[6];
    float* out = (float*)d_out;

    static cudaStream_t s2 = nullptr;
    static cudaEvent_t evFork = nullptr, evJoin = nullptr;
    if (!s2) {
        cudaStreamCreateWithFlags(&s2, cudaStreamNonBlocking);
        cudaEventCreateWithFlags(&evFork, cudaEventDisableTiming);
        cudaEventCreateWithFlags(&evJoin, cudaEventDisableTiming);
    }

    cudaEventRecord(evFork, 0);
    cudaStreamWaitEvent(s2, evFork, 0);
    gemm_kernel<<<2960, 256, 0, s2>>>(x, Wc, Wd);
    cudaEventRecord(evJoin, s2);

    detect_zero_kernel<<<NBLK, 256>>>((const unsigned int*)ei);
    hist_kernel<<<(N_EDGES / 2 + 255) / 256, 256>>>(ei);
    scan_local_kernel<<<NBLK, 256>>>();
    scan_block_kernel<<<1, 256>>>();
    finalize_kernel<<<NBLK, 256>>>(flux);
    fill_kernel<<<(N_EDGES + 255) / 256, 256>>>(ei, fdo);

    cudaStreamWaitEvent(0, evJoin, 0);
    gather_kernel<<<(BATCH * N_NODES * 32 + 255) / 256, 256>>>(bias, out);
}

// round 10
// speedup vs baseline: 1.4829x; 1.0573x over previous
#include <cuda_runtime.h>
#include <cuda_fp16.h>
#include <math.h>

#define N_NODES 50000
#define N_EDGES 1600000
#define BATCH   2
#define C       64
#define NBLK    ((N_NODES + 255) / 256)

// ---- scratch ----
__device__ int    g_cnt[N_NODES];
__device__ int    g_off[N_NODES + 1];
__device__ int    g_cursor[N_NODES];
__device__ int    g_bsum[NBLK];
__device__ int    g_bpre[NBLK];
__device__ float4 g_ni[N_NODES];      // {flux_b0, flux_b1, dis, 0}
// interleaved per (batch,node) row: [xc: 64 halfs][xd: 64 halfs] = 256 B
__device__ __align__(16) __half g_xi[(size_t)BATCH * N_NODES * 2 * C];
// unified edge metadata (CSR order): {src(int bits), norm, cC_b0, cC_b1}
__device__ float4 g_em[N_EDGES];
__device__ int    g_is64;

// ---- packed f32x2 helpers ----
__device__ __forceinline__ unsigned long long pk2(float x, float y) {
    unsigned long long r;
    asm("mov.b64 %0, {%1,%2};" : "=l"(r) : "f"(x), "f"(y));
    return r;
}
__device__ __forceinline__ void upk2(unsigned long long v, float& x, float& y) {
    asm("mov.b64 {%0,%1}, %2;" : "=f"(x), "=f"(y) : "l"(v));
}
__device__ __forceinline__ void fma2(unsigned long long& c,
                                     unsigned long long a,
                                     unsigned long long b) {
    asm("fma.rn.f32x2 %0, %1, %2, %0;" : "+l"(c) : "l"(a), "l"(b));
}
__device__ __forceinline__ void add2(unsigned long long& c, unsigned long long a) {
    asm("add.rn.f32x2 %0, %0, %1;" : "+l"(c) : "l"(a));
}
__device__ __forceinline__ float tanh_fast(float x) {
    asm("tanh.approx.f32 %0, %0;" : "+f"(x));
    return x;
}

// ---------------------------------------------------------------------------
__global__ void detect_zero_kernel(const unsigned int* __restrict__ w) {
    int i = blockIdx.x * blockDim.x + threadIdx.x;
    if (i < N_NODES) g_cnt[i] = 0;
    if (blockIdx.x == 0) {
        __shared__ unsigned int acc;
        if (threadIdx.x == 0) acc = 0u;
        __syncthreads();
        unsigned int v = 0u;
        for (int j = threadIdx.x; j < 4096; j += blockDim.x)
            v |= w[(size_t)2 * j * 97 + 1];
        atomicOr(&acc, v);
        __syncthreads();
        if (threadIdx.x == 0) g_is64 = (acc == 0u) ? 1 : 0;
    }
}

__device__ __forceinline__ int load_idx(const int* __restrict__ ei, size_t e) {
    return g_is64 ? ei[2 * e] : ei[e];
}

// 4 edges per thread
__global__ void hist_kernel(const int* __restrict__ ei) {
    int e4 = (blockIdx.x * blockDim.x + threadIdx.x) * 4;
    if (e4 >= N_EDGES) return;
    int t0, t1, t2, t3;
    if (g_is64) {
        const int4 v0 = *(const int4*)(ei + 2 * ((size_t)N_EDGES + e4));
        const int4 v1 = *(const int4*)(ei + 2 * ((size_t)N_EDGES + e4) + 4);
        t0 = v0.x; t1 = v0.z; t2 = v1.x; t3 = v1.z;
    } else {
        const int4 v = *(const int4*)(ei + (size_t)N_EDGES + e4);
        t0 = v.x; t1 = v.y; t2 = v.z; t3 = v.w;
    }
    atomicAdd(&g_cnt[t0], 1);
    atomicAdd(&g_cnt[t1], 1);
    atomicAdd(&g_cnt[t2], 1);
    atomicAdd(&g_cnt[t3], 1);
}

// ---------------------------------------------------------------------------
__device__ __forceinline__ int warp_incl_scan(int x) {
#pragma unroll
    for (int d = 1; d < 32; d <<= 1) {
        int y = __shfl_up_sync(0xffffffffu, x, d);
        if ((threadIdx.x & 31) >= d) x += y;
    }
    return x;
}

__global__ void __launch_bounds__(256) scan_local_kernel() {
    int i = blockIdx.x * 256 + threadIdx.x;
    int v = (i < N_NODES) ? g_cnt[i] : 0;
    int lane = threadIdx.x & 31, wid = threadIdx.x >> 5;
    int x = warp_incl_scan(v);
    __shared__ int wsum[8];
    if (lane == 31) wsum[wid] = x;
    __syncthreads();
    if (wid == 0) {
        int s = (lane < 8) ? wsum[lane] : 0;
#pragma unroll
        for (int d = 1; d < 8; d <<= 1) {
            int y = __shfl_up_sync(0xffffffffu, s, d);
            if (lane >= d) s += y;
        }
        if (lane < 8) wsum[lane] = s;
    }
    __syncthreads();
    int incl = x + (wid > 0 ? wsum[wid - 1] : 0);
    if (i < N_NODES) g_off[i] = incl - v;
    if (threadIdx.x == 255) g_bsum[blockIdx.x] = incl;
}

__global__ void __launch_bounds__(256) scan_block_kernel() {
    int t = threadIdx.x;
    int v = (t < NBLK) ? g_bsum[t] : 0;
    int lane = t & 31, wid = t >> 5;
    int x = warp_incl_scan(v);
    __shared__ int wsum[8];
    if (lane == 31) wsum[wid] = x;
    __syncthreads();
    if (wid == 0) {
        int s = (lane < 8) ? wsum[lane] : 0;
#pragma unroll
        for (int d = 1; d < 8; d <<= 1) {
            int y = __shfl_up_sync(0xffffffffu, s, d);
            if (lane >= d) s += y;
        }
        if (lane < 8) wsum[lane] = s;
    }
    __syncthreads();
    int incl = x + (wid > 0 ? wsum[wid - 1] : 0);
    if (t < NBLK) g_bpre[t] = incl - v;
}

__global__ void finalize_kernel(const float* __restrict__ fluxes) {
    int i = blockIdx.x * blockDim.x + threadIdx.x;
    if (i < N_NODES) {
        int off = g_off[i] + g_bpre[i >> 8];
        g_off[i] = off;
        g_cursor[i] = off;
        const float dis = rsqrtf((float)(g_cnt[i] + 1));
        g_ni[i] = make_float4(fluxes[i], fluxes[N_NODES + i], dis, 0.0f);
    }
    if (i == 0) g_off[N_NODES] = N_EDGES;
}

// ---------------------------------------------------------------------------
// fill CSR buckets: single 16 B meta per edge serving both batches.
// cD_b = norm - cC_b (exact).
// ---------------------------------------------------------------------------
__global__ void __launch_bounds__(256)
fill_kernel(const int* __restrict__ ei,
            const float* __restrict__ fdo) {
    int e = blockIdx.x * blockDim.x + threadIdx.x;
    if (e >= N_EDGES) return;
    int s = load_idx(ei, e);
    int t = load_idx(ei, (size_t)N_EDGES + e);

    int pos = atomicAdd(&g_cursor[t], 1);

    const float4 nis = __ldg(&g_ni[s]);
    const float4 nit = __ldg(&g_ni[t]);

    const float f0   = fdo[e];
    const float norm = nis.z * nit.z;

    const float k0 = 0.5f * (1.0f + tanh_fast(nis.x * nit.x));
    const float k1 = 0.5f * (1.0f + tanh_fast(nis.y * nit.y));
    const float fb0 = k0 * f0 + (1.0f - k0) * (1.0f - f0);
    const float fb1 = k1 * f0 + (1.0f - k1) * (1.0f - f0);

    g_em[pos] = make_float4(__int_as_float(s), norm,
                            norm * (1.0f - fb0), norm * (1.0f - fb1));
}

// ---------------------------------------------------------------------------
// Dual GEMM -> interleaved fp16 rows [xc(64)|xd(64)]. FFMA2-packed.
// ---------------------------------------------------------------------------
__global__ void __launch_bounds__(256)
gemm_kernel(const float* __restrict__ x,
            const float* __restrict__ Wc,
            const float* __restrict__ Wd) {
    const int o  = threadIdx.x >> 2;
    const int kg = threadIdx.x & 3;

    unsigned long long wp[16];
#pragma unroll
    for (int i = 0; i < 16; i++)
        wp[i] = pk2(Wc[o * C + kg * 16 + i], Wd[o * C + kg * 16 + i]);

    __shared__ __align__(16) float xs[4][C];
    const int M = BATCH * N_NODES;
    const int lr = threadIdx.x >> 6;
    const int lc = threadIdx.x & 63;

    for (int m0 = blockIdx.x * 4; m0 < M; m0 += gridDim.x * 4) {
        __syncthreads();
        xs[lr][lc] = x[(size_t)(m0 + lr) * C + lc];
        __syncthreads();

#pragma unroll
        for (int r2 = 0; r2 < 4; r2++) {
            const float4* xp = (const float4*)&xs[r2][kg * 16];
            unsigned long long acc = 0ull;
#pragma unroll
            for (int j = 0; j < 4; j++) {
                float4 xv = xp[j];
                fma2(acc, pk2(xv.x, xv.x), wp[4 * j + 0]);
                fma2(acc, pk2(xv.y, xv.y), wp[4 * j + 1]);
                fma2(acc, pk2(xv.z, xv.z), wp[4 * j + 2]);
                fma2(acc, pk2(xv.w, xv.w), wp[4 * j + 3]);
            }
            float sc, sd;
            upk2(acc, sc, sd);
            sc += __shfl_xor_sync(0xffffffffu, sc, 1);
            sc += __shfl_xor_sync(0xffffffffu, sc, 2);
            sd += __shfl_xor_sync(0xffffffffu, sd, 1);
            sd += __shfl_xor_sync(0xffffffffu, sd, 2);
            float sc2 = __shfl_xor_sync(0xffffffffu, sc, 4);
            float sd2 = __shfl_xor_sync(0xffffffffu, sd, 4);

            if (kg == 0 && (o & 1) == 0) {
                __half* row = g_xi + (size_t)(m0 + r2) * (2 * C);
                *(__half2*)(row + o)     = __floats2half2_rn(sc, sc2);
                *(__half2*)(row + C + o) = __floats2half2_rn(sd, sd2);
            }
        }
    }
}

// ---------------------------------------------------------------------------
// Gather: 128-thread blocks (higher blocks/SM => more resident warps).
// One warp per (node,batch), batch-major. Four 8-lane groups; 4 edges per
// trip, all 8 row LDG.128s issued up front. fp16 core, flush every 2 edges.
// Branch-free tail via index clamp + coefficient zeroing.
// ---------------------------------------------------------------------------
__global__ void __launch_bounds__(128)
gather_kernel(const float* __restrict__ bias, float* __restrict__ out) {
    const int w = (int)((blockIdx.x * blockDim.x + threadIdx.x) >> 5);
    if (w >= BATCH * N_NODES) return;
    const int b    = (w < N_NODES) ? 0 : 1;
    const int n    = (w < N_NODES) ? w : (w - N_NODES);
    const int lane = threadIdx.x & 31;
    const int g    = lane >> 3;        // edge group 0..3
    const int l8   = lane & 7;         // 8 channels: l8*8 .. +8

    const int beg = g_off[n];
    const int end = g_off[n + 1];

    const __half*  __restrict__ xib = g_xi + (size_t)b * N_NODES * (2 * C);

    unsigned long long a0 = 0ull, a1 = 0ull, a2 = 0ull, a3 = 0ull;

    if (g == 0) {   // self-loop + bias init
        const float4 ni = g_ni[n];
        const float nrm = ni.z * ni.z;
        const float4 b0 = *(const float4*)(bias + l8 * 8);
        const float4 b1 = *(const float4*)(bias + l8 * 8 + 4);
        const uint4  xh = *(const uint4*)(xib + (size_t)n * (2 * C) + l8 * 8);
        const float2 x0 = __half22float2(*(const __half2*)&xh.x);
        const float2 x1 = __half22float2(*(const __half2*)&xh.y);
        const float2 x2 = __half22float2(*(const __half2*)&xh.z);
        const float2 x3 = __half22float2(*(const __half2*)&xh.w);
        a0 = pk2(fmaf(nrm, x0.x, b0.x), fmaf(nrm, x0.y, b0.y));
        a1 = pk2(fmaf(nrm, x1.x, b0.z), fmaf(nrm, x1.y, b0.w));
        a2 = pk2(fmaf(nrm, x2.x, b1.x), fmaf(nrm, x2.y, b1.y));
        a3 = pk2(fmaf(nrm, x3.x, b1.z), fmaf(nrm, x3.y, b1.w));
    }

    int i = beg + g;                   // this group's slots: i, i+4, i+8, i+12
    if (i < end) {
        const int last = end - 1;
        // per-edge state: (src, cC, cD) with cD = norm - cC
        float3 m[4];
#pragma unroll
        for (int k = 0; k < 4; k++) {
            const int  j = i + 4 * k;
            const bool v = (j < end);
            const float4 t = __ldg(&g_em[v ? j : last]);
            const float cC = v ? (b ? t.w : t.z) : 0.0f;
            const float nm = v ? t.y : 0.0f;
            m[k] = make_float3(t.x, cC, nm - cC);
        }

        for (;;) {
            // 1) issue all 8 row loads (max lines in flight)
            uint4 A[4], D[4];
#pragma unroll
            for (int k = 0; k < 4; k++) {
                const __half* row = xib +
                    (size_t)__float_as_int(m[k].x) * (2 * C) + l8 * 8;
                A[k] = __ldg((const uint4*)(row));
                D[k] = __ldg((const uint4*)(row + C));
            }

            // 2) prefetch next 4 metas (clamped; harmless when exiting)
            i += 16;
            const bool more = (i < end);
            float3 mn[4];
#pragma unroll
            for (int k = 0; k < 4; k++) {
                const int  j = i + 4 * k;
                const bool v = (j < end);
                const float4 t = __ldg(&g_em[v ? j : last]);
                const float cC = v ? (b ? t.w : t.z) : 0.0f;
                const float nm = v ? t.y : 0.0f;
                mn[k] = make_float3(t.x, cC, nm - cC);
            }

            // 3) consume: fp16 core, flush every 2 edges
#pragma unroll
            for (int p = 0; p < 2; p++) {
                const int k0 = 2 * p, k1 = 2 * p + 1;
                const __half2 cc0 = __float2half2_rn(m[k0].y);
                const __half2 cd0 = __float2half2_rn(m[k0].z);
                const __half2 cc1 = __float2half2_rn(m[k1].y);
                const __half2 cd1 = __float2half2_rn(m[k1].z);
                const __half2* A0 = (const __half2*)&A[k0];
                const __half2* D0 = (const __half2*)&D[k0];
                const __half2* A1 = (const __half2*)&A[k1];
                const __half2* D1 = (const __half2*)&D[k1];

                __half2 h0 = __hmul2(A0[0], cc0);
                __half2 h1 = __hmul2(A0[1], cc0);
                __half2 h2 = __hmul2(A0[2], cc0);
                __half2 h3 = __hmul2(A0[3], cc0);
                h0 = __hfma2(D0[0], cd0, h0);
                h1 = __hfma2(D0[1], cd0, h1);
                h2 = __hfma2(D0[2], cd0, h2);
                h3 = __hfma2(D0[3], cd0, h3);
                h0 = __hfma2(A1[0], cc1, h0);
                h1 = __hfma2(A1[1], cc1, h1);
                h2 = __hfma2(A1[2], cc1, h2);
                h3 = __hfma2(A1[3], cc1, h3);
                h0 = __hfma2(D1[0], cd1, h0);
                h1 = __hfma2(D1[1], cd1, h1);
                h2 = __hfma2(D1[2], cd1, h2);
                h3 = __hfma2(D1[3], cd1, h3);

                float2 f;
                f = __half22float2(h0); add2(a0, pk2(f.x, f.y));
                f = __half22float2(h1); add2(a1, pk2(f.x, f.y));
                f = __half22float2(h2); add2(a2, pk2(f.x, f.y));
                f = __half22float2(h3); add2(a3, pk2(f.x, f.y));
            }

            if (!more) break;
#pragma unroll
            for (int k = 0; k < 4; k++) m[k] = mn[k];
        }
    }

    // reduce the 4 groups
    float f0, f1, f2, f3, f4, f5, f6, f7;
    upk2(a0, f0, f1); upk2(a1, f2, f3); upk2(a2, f4, f5); upk2(a3, f6, f7);
#pragma unroll
    for (int d = 8; d <= 16; d <<= 1) {
        f0 += __shfl_xor_sync(0xffffffffu, f0, d);
        f1 += __shfl_xor_sync(0xffffffffu, f1, d);
        f2 += __shfl_xor_sync(0xffffffffu, f2, d);
        f3 += __shfl_xor_sync(0xffffffffu, f3, d);
        f4 += __shfl_xor_sync(0xffffffffu, f4, d);
        f5 += __shfl_xor_sync(0xffffffffu, f5, d);
        f6 += __shfl_xor_sync(0xffffffffu, f6, d);
        f7 += __shfl_xor_sync(0xffffffffu, f7, d);
    }

    if (g == 0) {
        float* orow = out + ((size_t)b * N_NODES + n) * C + l8 * 8;
        *(float4*)(orow)     = make_float4(f0, f1, f2, f3);
        *(float4*)(orow + 4) = make_float4(f4, f5, f6, f7);
    }
}

// ---------------------------------------------------------------------------
extern "C" void kernel_launch(void* const* d_in, const int* in_sizes, int n_in,
                              void* d_out, int out_size) {
    const float* x    = (const float*)d_in[0];
    const int*   ei   = (const int*)d_in[1];
    const float* fdo  = (const float*)d_in[2];
    const float* flux = (const float*)d_in[3];
    const float* Wc   = (const float*)d_in[4];
    const float* Wd   = (const float*)d_in[5];
    const float* bias = (const float*)d_in[6];
    float* out = (float*)d_out;

    static cudaStream_t s2 = nullptr;
    static cudaEvent_t evFork = nullptr, evJoin = nullptr;
    if (!s2) {
        cudaStreamCreateWithFlags(&s2, cudaStreamNonBlocking);
        cudaEventCreateWithFlags(&evFork, cudaEventDisableTiming);
        cudaEventCreateWithFlags(&evJoin, cudaEventDisableTiming);
    }

    cudaEventRecord(evFork, 0);
    cudaStreamWaitEvent(s2, evFork, 0);
    gemm_kernel<<<2960, 256, 0, s2>>>(x, Wc, Wd);
    cudaEventRecord(evJoin, s2);

    detect_zero_kernel<<<NBLK, 256>>>((const unsigned int*)ei);
    hist_kernel<<<(N_EDGES / 4 + 255) / 256, 256>>>(ei);
    scan_local_kernel<<<NBLK, 256>>>();
    scan_block_kernel<<<1, 256>>>();
    finalize_kernel<<<NBLK, 256>>>(flux);
    fill_kernel<<<(N_EDGES + 255) / 256, 256>>>(ei, fdo);

    cudaStreamWaitEvent(0, evJoin, 0);
    gather_kernel<<<(BATCH * N_NODES * 32 + 127) / 128, 128>>>(bias, out);
}